// round 15
// baseline (speedup 1.0000x reference)
#include <cuda_runtime.h>
#include <cstdint>

#define B_TOTAL 262144
#define D_DIM   64
#define NR      32
#define NC      32
#define SN      32
#define ZN      32

#define NTHR    192
#define NWARP   6
#define NGRID   1366      // ceil(262144/192); tail block has 2 valid warps

typedef unsigned long long u64t;

// shared memory layout in floats
#define SM_WPZ   0          // 1024  W_pz[z][j]
#define SM_WR    1024       // 4096  W_real[r][o][d] (transposed)
#define SM_WC    5120       // 8192  W_cat[c][k][d]  (transposed)
#define SM_BPZ   13312      // 32
#define SM_BR    13344      // 64
#define SM_BC    13408      // 128
#define SM_TILE  13536      // 6 warps x 640 floats (32 rows x 20 stride)
#define SM_TOTAL 17376      // floats -> 69504 bytes (x3 CTAs = 208.5KB <= 228KB)

// ---------------- packed f32x2 helpers ----------------
__device__ __forceinline__ u64t ffma2(u64t a, u64t b, u64t c) {
    u64t d;
    asm("fma.rn.f32x2 %0, %1, %2, %3;" : "=l"(d) : "l"(a), "l"(b), "l"(c));
    return d;
}
__device__ __forceinline__ float pair_sum(u64t v) {
    unsigned lo, hi;
    asm("mov.b64 {%0, %1}, %2;" : "=r"(lo), "=r"(hi) : "l"(v));
    return __uint_as_float(lo) + __uint_as_float(hi);
}

// ---------------- threefry2x32 (JAX schedule) ----------------
#define TF_ROUND(r) do { x0 += x1; x1 = (x1 << (r)) | (x1 >> (32 - (r))); x1 ^= x0; } while (0)

__host__ __device__ __forceinline__ void threefry_full(unsigned k0, unsigned k1,
                                                       unsigned x0, unsigned x1,
                                                       unsigned &o0, unsigned &o1) {
    const unsigned k2 = k0 ^ k1 ^ 0x1BD11BDAu;
    x0 += k0; x1 += k1;
    TF_ROUND(13); TF_ROUND(15); TF_ROUND(26); TF_ROUND(6);
    x0 += k1; x1 += k2 + 1u;
    TF_ROUND(17); TF_ROUND(29); TF_ROUND(16); TF_ROUND(24);
    x0 += k2; x1 += k0 + 2u;
    TF_ROUND(13); TF_ROUND(15); TF_ROUND(26); TF_ROUND(6);
    x0 += k0; x1 += k1 + 3u;
    TF_ROUND(17); TF_ROUND(29); TF_ROUND(16); TF_ROUND(24);
    x0 += k1; x1 += k2 + 4u;
    TF_ROUND(13); TF_ROUND(15); TF_ROUND(26); TF_ROUND(6);
    x0 += k2; x1 += k0 + 5u;
    o0 = x0; o1 = x1;
}

// Partitionable threefry sample: counter (hi=0, lo=ctr), folded o0^o1.
__device__ __forceinline__ unsigned tf_fold(unsigned k0, unsigned k1, unsigned k2,
                                            unsigned ctr) {
    unsigned x0 = k0;
    unsigned x1 = ctr + k1;
    TF_ROUND(13); TF_ROUND(15); TF_ROUND(26); TF_ROUND(6);
    x0 += k1; x1 += k2 + 1u;
    TF_ROUND(17); TF_ROUND(29); TF_ROUND(16); TF_ROUND(24);
    x0 += k2; x1 += k0 + 2u;
    TF_ROUND(13); TF_ROUND(15); TF_ROUND(26); TF_ROUND(6);
    x0 += k0; x1 += k1 + 3u;
    TF_ROUND(17); TF_ROUND(29); TF_ROUND(16); TF_ROUND(24);
    x0 += k1; x1 += k2 + 4u;
    TF_ROUND(13); TF_ROUND(15); TF_ROUND(26); TF_ROUND(6);
    x0 += k2; x1 += k0 + 5u;
    return x0 ^ x1;
}

// bits -> float in [0, 1-2^-23]
__device__ __forceinline__ float bits_to_unit(unsigned b) {
    return __uint_as_float((b >> 9) | 0x3f800000u) - 1.0f;
}

// XLA ErfInv32 (Giles polynomial), fast-log variant
__device__ __forceinline__ float erfinv_xla(float x) {
    float w = -__logf(fmaf(-x, x, 1.0f));
    float p;
    if (w < 5.0f) {
        w = w - 2.5f;
        p = 2.81022636e-08f;
        p = fmaf(p, w, 3.43273939e-07f);
        p = fmaf(p, w, -3.5233877e-06f);
        p = fmaf(p, w, -4.39150654e-06f);
        p = fmaf(p, w, 0.00021858087f);
        p = fmaf(p, w, -0.00125372503f);
        p = fmaf(p, w, -0.00417768164f);
        p = fmaf(p, w, 0.246640727f);
        p = fmaf(p, w, 1.50140941f);
    } else {
        w = sqrtf(w) - 3.0f;
        p = -0.000200214257f;
        p = fmaf(p, w, 0.000100950558f);
        p = fmaf(p, w, 0.00134934322f);
        p = fmaf(p, w, -0.00367342844f);
        p = fmaf(p, w, 0.00573950773f);
        p = fmaf(p, w, -0.0076224613f);
        p = fmaf(p, w, 0.00943887047f);
        p = fmaf(p, w, 1.00167406f);
        p = fmaf(p, w, 2.83297682f);
    }
    return p * x;
}

__device__ __forceinline__ float normal_from_bits(unsigned b) {
    float f = bits_to_unit(b);
    float u = fmaf(f, 2.0f, -0.99999994f);
    u = fmaxf(-0.99999994f, u);
    return 1.41421356f * erfinv_xla(u);
}

__device__ __forceinline__ float gumbel_from_bits(unsigned b) {
    float f = bits_to_unit(b);
    float t = -__logf(fmaxf(f, 1.17549435e-38f));
    t = fmaxf(t, 1.17549435e-38f);
    return -__logf(t);
}

__device__ __forceinline__ void cat_row(float l1, float l2, float l3, float l4,
                                        const unsigned gb[5],
                                        const float* __restrict__ data5, float miss,
                                        float &out_val, float &lp_val) {
    float m = fmaxf(0.0f, fmaxf(fmaxf(l1, l2), fmaxf(l3, l4)));
    float e0 = __expf(0.0f - m);
    float e1 = __expf(l1 - m);
    float e2 = __expf(l2 - m);
    float e3 = __expf(l3 - m);
    float e4 = __expf(l4 - m);
    float S  = ((e0 + e1) + (e2 + e3)) + e4;
    float logS = __logf(S);
    float lp =            data5[0] * ((0.0f - m) - logS);
    lp = fmaf(data5[1], (l1 - m) - logS, lp);
    lp = fmaf(data5[2], (l2 - m) - logS, lp);
    lp = fmaf(data5[3], (l3 - m) - logS, lp);
    lp = fmaf(data5[4], (l4 - m) - logS, lp);
    lp_val = lp * miss;

    float z0 = gumbel_from_bits(gb[0]);
    float z1 = l1 + gumbel_from_bits(gb[1]);
    float z2 = l2 + gumbel_from_bits(gb[2]);
    float z3 = l3 + gumbel_from_bits(gb[3]);
    float z4 = l4 + gumbel_from_bits(gb[4]);
    float best = z0; int arg = 0;
    if (z1 > best) { best = z1; arg = 1; }
    if (z2 > best) { best = z2; arg = 2; }
    if (z3 > best) { best = z3; arg = 3; }
    if (z4 > best) { best = z4; arg = 4; }
    out_val = (float)arg;
}

// Coalesced flush: 32 rows x 16 tile cols -> gmem.
__device__ __forceinline__ void flush_tile(const float* tile, float* gbase,
                                           int stride, int c0, int lane) {
#pragma unroll
    for (int it = 0; it < 4; it++) {
        const int row = it * 8 + (lane >> 2);
        const int col = (lane & 3) * 4;
        float4 v = *(const float4*)(tile + row * 20 + col);
        *(float4*)(gbase + (size_t)row * stride + c0 + col) = v;
    }
}

// Coalesced flush: 32 rows x 8 tile cols (tcol..tcol+7) -> gmem (stride 64).
__device__ __forceinline__ void flush8(const float* tile, float* gbase,
                                       int tcol, int gcol, int lane) {
#pragma unroll
    for (int it = 0; it < 2; it++) {
        const int row = it * 16 + (lane >> 1);
        const int col = (lane & 1) * 4;
        float4 v = *(const float4*)(tile + row * 20 + tcol + col);
        *(float4*)(gbase + (size_t)row * 64 + gcol + col) = v;
    }
}

__global__ __launch_bounds__(NTHR, 3)
void decoder_kernel(const float* __restrict__ y_lat, const float* __restrict__ samp_s,
                    const float* __restrict__ onehot, const int* __restrict__ miss_mask,
                    const float* __restrict__ W_pz, const float* __restrict__ b_pz,
                    const float* __restrict__ W_real, const float* __restrict__ b_real,
                    const float* __restrict__ W_cat, const float* __restrict__ b_cat,
                    float* __restrict__ out,
                    unsigned kn0, unsigned kn1, unsigned kn2,
                    unsigned kg0, unsigned kg1, unsigned kg2) {
    extern __shared__ float sm[];
    {
        const int tid = threadIdx.x;
        for (int i = tid; i < 256; i += NTHR)
            ((float4*)(sm + SM_WPZ))[i] = ((const float4*)W_pz)[i];
        // transpose W_real [r][d][o] -> [r][o][d]
        for (int i = tid; i < 4096; i += NTHR) {
            int r = i >> 7, o = (i >> 6) & 1, d = i & 63;
            sm[SM_WR + i] = W_real[(r << 7) + (d << 1) + o];
        }
        // transpose W_cat [c][d][k] -> [c][k][d]
        for (int i = tid; i < 8192; i += NTHR) {
            int c = i >> 8, k = (i >> 6) & 3, d = i & 63;
            sm[SM_WC + i] = W_cat[(c << 8) + (d << 2) + k];
        }
        for (int i = tid; i < 8; i += NTHR)
            ((float4*)(sm + SM_BPZ))[i] = ((const float4*)b_pz)[i];
        for (int i = tid; i < 16; i += NTHR)
            ((float4*)(sm + SM_BR))[i] = ((const float4*)b_real)[i];
        for (int i = tid; i < 32; i += NTHR)
            ((float4*)(sm + SM_BC))[i] = ((const float4*)b_cat)[i];
    }
    __syncthreads();

    const int b = blockIdx.x * NTHR + threadIdx.x;
    const int lane = threadIdx.x & 31;
    const int warp = threadIdx.x >> 5;
    const int rowbase = b & ~31;
    if (rowbase >= B_TOTAL) return;            // warp-aligned tail guard

    float* tile = sm + SM_TILE + warp * 640;   // 32 rows x 20 stride

    float* o_out = out;
    float* o_mpz = out + (size_t)B_TOTAL * 64;
    float* o_lvz = out + (size_t)B_TOTAL * 96;
    float* o_lpx = out + (size_t)B_TOTAL * 128;

    // ================= pz: mean_pz = s @ W_pz^T + b_pz =================
    {
        u64t s2[16];
        const ulonglong2* ps = (const ulonglong2*)(samp_s + (size_t)b * SN);
#pragma unroll
        for (int i = 0; i < 8; i++) {
            ulonglong2 v = ps[i]; s2[2*i] = v.x; s2[2*i+1] = v.y;
        }
#pragma unroll 1
        for (int z = 0; z < ZN; z++) {
            u64t acc = 0;
            const ulonglong2* w = (const ulonglong2*)(sm + SM_WPZ + z * SN);
#pragma unroll
            for (int j = 0; j < 8; j++) {   // 8 x 4 floats = 32 = SN
                ulonglong2 v = w[j];
                acc = ffma2(s2[2*j],   v.x, acc);
                acc = ffma2(s2[2*j+1], v.y, acc);
            }
            tile[lane * 20 + (z & 15)] = sm[SM_BPZ + z] + pair_sum(acc);
            if ((z & 15) == 15) {
                __syncwarp();
                flush_tile(tile, o_mpz + (size_t)rowbase * 32, 32, z & 16, lane);
                __syncwarp();
            }
        }
    }

    // ================= log_var_pz = 0 (coalesced direct stores) =================
    {
        const float4 z4 = make_float4(0.f, 0.f, 0.f, 0.f);
        float* base = o_lvz + (size_t)rowbase * 32;
#pragma unroll
        for (int it = 0; it < 8; it++) {
            const int row = it * 4 + (lane >> 3);
            const int col = (lane & 7) * 4;
            *(float4*)(base + (size_t)row * 32 + col) = z4;
        }
    }

    // ================= load y as K-pairs (register resident) =================
    u64t y2[32];
    {
        const ulonglong2* py = (const ulonglong2*)(y_lat + (size_t)b * D_DIM);
#pragma unroll
        for (int i = 0; i < 16; i++) {
            ulonglong2 v = py[i]; y2[2*i] = v.x; y2[2*i+1] = v.y;
        }
    }

    // ================= real features (4 per iter; flush 8 per 2 iters) =========
#pragma unroll 1
    for (int r4 = 0; r4 < NR; r4 += 4) {
        float4 d4 = *(const float4*)(onehot + (size_t)b * 192 + r4);
        int4  ms4 = *(const int4*)(miss_mask + (size_t)b * 64 + r4);
        float darr[4] = {d4.x, d4.y, d4.z, d4.w};
        int   marr[4] = {ms4.x, ms4.y, ms4.z, ms4.w};
        float outv[4], lpv[4];
#pragma unroll
        for (int rr = 0; rr < 4; rr++) {
            const int r = r4 + rr;
            u64t am = 0, av = 0;
            const ulonglong2* wm = (const ulonglong2*)(sm + SM_WR + r * 128);
            const ulonglong2* wv = wm + 16;   // +64 floats
#pragma unroll
            for (int j = 0; j < 16; j++) {    // 16 x 4 floats = 64 = D_DIM
                ulonglong2 m2 = wm[j], v2 = wv[j];
                am = ffma2(y2[2*j],   m2.x, am);
                am = ffma2(y2[2*j+1], m2.y, am);
                av = ffma2(y2[2*j],   v2.x, av);
                av = ffma2(y2[2*j+1], v2.y, av);
            }
            const float mu = sm[SM_BR + 2*r]     + pair_sum(am);
            const float lv = sm[SM_BR + 2*r + 1] + pair_sum(av);

            const float nz = normal_from_bits(tf_fold(kn0, kn1, kn2,
                                              (unsigned)b * 32u + (unsigned)r));
            float dv = darr[rr]; if (dv != dv) dv = 0.f;   // nan_to_num
            const float miss = (float)marr[rr];
            const float diff = dv - mu;
            lpv[rr]  = -0.5f * ((1.8378770664f + lv) + diff * diff * __expf(-lv)) * miss;
            outv[rr] = fmaf(__expf(0.5f * lv), nz, mu);
        }
        const int cb = r4 & 4;                 // 0 or 4
        *(float4*)(tile + lane * 20 + cb)     = make_float4(outv[0], outv[1], outv[2], outv[3]);
        *(float4*)(tile + lane * 20 + 8 + cb) = make_float4(lpv[0], lpv[1], lpv[2], lpv[3]);
        if (cb) {                              // 8 features staged -> flush
            __syncwarp();
            const int c0 = r4 & ~7;            // 0,8,16,24
            flush8(tile, o_out + (size_t)rowbase * 64, 0, c0, lane);
            flush8(tile, o_lpx + (size_t)rowbase * 64, 8, c0, lane);
            __syncwarp();
        }
    }

    // ================= categorical features (4 per iter; flush 8 per 2 iters) ==
#pragma unroll 1
    for (int g = 0; g < 8; g++) {
        const float4* pd4 = (const float4*)(onehot + (size_t)b * 192 + 32 + 20 * g);
        float dat[20];
        *(float4*)(dat +  0) = pd4[0];
        *(float4*)(dat +  4) = pd4[1];
        *(float4*)(dat +  8) = pd4[2];
        *(float4*)(dat + 12) = pd4[3];
        *(float4*)(dat + 16) = pd4[4];
        int4 ms = *(const int4*)(miss_mask + (size_t)b * 64 + 32 + 4 * g);
        int marr[4] = {ms.x, ms.y, ms.z, ms.w};
#pragma unroll
        for (int cc = 0; cc < 4; cc++) {
            const int c = 4 * g + cc;
            u64t a1 = 0, a2 = 0, a3 = 0, a4 = 0;
            const ulonglong2* w1 = (const ulonglong2*)(sm + SM_WC + c * 256);
            const ulonglong2* w2 = w1 + 16;
            const ulonglong2* w3 = w1 + 32;
            const ulonglong2* w4 = w1 + 48;
#pragma unroll
            for (int j = 0; j < 16; j++) {
                ulonglong2 p1 = w1[j], p2 = w2[j], p3 = w3[j], p4 = w4[j];
                a1 = ffma2(y2[2*j],   p1.x, a1);
                a1 = ffma2(y2[2*j+1], p1.y, a1);
                a2 = ffma2(y2[2*j],   p2.x, a2);
                a2 = ffma2(y2[2*j+1], p2.y, a2);
                a3 = ffma2(y2[2*j],   p3.x, a3);
                a3 = ffma2(y2[2*j+1], p3.y, a3);
                a4 = ffma2(y2[2*j],   p4.x, a4);
                a4 = ffma2(y2[2*j+1], p4.y, a4);
            }
            float4 bc = *(const float4*)(sm + SM_BC + 4 * c);
            const float l1 = bc.x + pair_sum(a1);
            const float l2 = bc.y + pair_sum(a2);
            const float l3 = bc.z + pair_sum(a3);
            const float l4 = bc.w + pair_sum(a4);

            const unsigned base = ((unsigned)b * 32u + (unsigned)c) * 5u;
            unsigned gb[5];
#pragma unroll
            for (int k = 0; k < 5; k++)
                gb[k] = tf_fold(kg0, kg1, kg2, base + (unsigned)k);

            float dat5[5];
#pragma unroll
            for (int k = 0; k < 5; k++) dat5[k] = dat[5 * cc + k];

            float ov, lpval;
            cat_row(l1, l2, l3, l4, gb, dat5, (float)marr[cc], ov, lpval);

            tile[lane * 20 + (c & 7)]     = ov;
            tile[lane * 20 + 8 + (c & 7)] = lpval;
        }
        if (g & 1) {                           // 8 features staged -> flush
            __syncwarp();
            const int c0 = 32 + ((g >> 1) << 3);   // 32,40,48,56
            flush8(tile, o_out + (size_t)rowbase * 64, 0, c0, lane);
            flush8(tile, o_lpx + (size_t)rowbase * 64, 8, c0, lane);
            __syncwarp();
        }
    }
}

extern "C" void kernel_launch(void* const* d_in, const int* in_sizes, int n_in,
                              void* d_out, int out_size) {
    const float* y_lat  = (const float*)d_in[0];
    const float* samp_s = (const float*)d_in[1];
    const float* onehot = (const float*)d_in[2];
    // d_in[3] = static_types (compile-time known layout; unused)
    const int*   mask   = (const int*)d_in[4];
    const float* W_pz   = (const float*)d_in[5];
    const float* b_pz   = (const float*)d_in[6];
    const float* W_real = (const float*)d_in[7];
    const float* b_real = (const float*)d_in[8];
    const float* W_cat  = (const float*)d_in[9];
    const float* b_cat  = (const float*)d_in[10];
    float* out = (float*)d_out;

    // jax.random.key(42) = (0, 42); partitionable (foldlike) split:
    // key_i = threefry((0,42), (0, i)), both output words form the subkey.
    unsigned kn0, kn1, kg0, kg1;
    threefry_full(0u, 42u, 0u, 0u, kn0, kn1);   // k_norm
    threefry_full(0u, 42u, 0u, 1u, kg0, kg1);   // k_gum
    const unsigned kn2 = kn0 ^ kn1 ^ 0x1BD11BDAu;
    const unsigned kg2 = kg0 ^ kg1 ^ 0x1BD11BDAu;

    cudaFuncSetAttribute(decoder_kernel,
                         cudaFuncAttributeMaxDynamicSharedMemorySize, SM_TOTAL * 4);
    decoder_kernel<<<NGRID, NTHR, SM_TOTAL * 4>>>(
        y_lat, samp_s, onehot, mask, W_pz, b_pz, W_real, b_real, W_cat, b_cat,
        out, kn0, kn1, kn2, kg0, kg1, kg2);
}

// round 16
// speedup vs baseline: 1.1511x; 1.1511x over previous
#include <cuda_runtime.h>
#include <cstdint>

#define B_TOTAL 262144
#define D_DIM   64
#define NR      32
#define NC      32
#define SN      32
#define ZN      32

typedef unsigned long long u64t;

// packed miss mask scratch: one 64-bit word per row
__device__ u64t g_packed_mask[B_TOTAL];

// shared memory layout in floats
#define SM_WPZ   0          // 1024  W_pz[z][j]
#define SM_WR    1024       // 4096  W_real[r][o][d] (transposed)
#define SM_WC    5120       // 8192  W_cat[c][k][d]  (transposed)
#define SM_BPZ   13312      // 32
#define SM_BR    13344      // 64
#define SM_BC    13408      // 128
#define SM_TILEA 13536      // 8 warps x 640 floats (32 rows x 20 stride)
#define SM_TILEB 18656      // 8 warps x 640 floats
#define SM_TOTAL 23776      // floats -> 95104 bytes

// ---------------- packed f32x2 helpers ----------------
__device__ __forceinline__ u64t ffma2(u64t a, u64t b, u64t c) {
    u64t d;
    asm("fma.rn.f32x2 %0, %1, %2, %3;" : "=l"(d) : "l"(a), "l"(b), "l"(c));
    return d;
}
__device__ __forceinline__ float pair_sum(u64t v) {
    unsigned lo, hi;
    asm("mov.b64 {%0, %1}, %2;" : "=r"(lo), "=r"(hi) : "l"(v));
    return __uint_as_float(lo) + __uint_as_float(hi);
}

// ---------------- threefry2x32 (JAX schedule) ----------------
#define TF_ROUND(r) do { x0 += x1; x1 = (x1 << (r)) | (x1 >> (32 - (r))); x1 ^= x0; } while (0)

__host__ __device__ __forceinline__ void threefry_full(unsigned k0, unsigned k1,
                                                       unsigned x0, unsigned x1,
                                                       unsigned &o0, unsigned &o1) {
    const unsigned k2 = k0 ^ k1 ^ 0x1BD11BDAu;
    x0 += k0; x1 += k1;
    TF_ROUND(13); TF_ROUND(15); TF_ROUND(26); TF_ROUND(6);
    x0 += k1; x1 += k2 + 1u;
    TF_ROUND(17); TF_ROUND(29); TF_ROUND(16); TF_ROUND(24);
    x0 += k2; x1 += k0 + 2u;
    TF_ROUND(13); TF_ROUND(15); TF_ROUND(26); TF_ROUND(6);
    x0 += k0; x1 += k1 + 3u;
    TF_ROUND(17); TF_ROUND(29); TF_ROUND(16); TF_ROUND(24);
    x0 += k1; x1 += k2 + 4u;
    TF_ROUND(13); TF_ROUND(15); TF_ROUND(26); TF_ROUND(6);
    x0 += k2; x1 += k0 + 5u;
    o0 = x0; o1 = x1;
}

// Partitionable threefry sample: counter (hi=0, lo=ctr), folded o0^o1.
__device__ __forceinline__ unsigned tf_fold(unsigned k0, unsigned k1, unsigned k2,
                                            unsigned ctr) {
    unsigned x0 = k0;
    unsigned x1 = ctr + k1;
    TF_ROUND(13); TF_ROUND(15); TF_ROUND(26); TF_ROUND(6);
    x0 += k1; x1 += k2 + 1u;
    TF_ROUND(17); TF_ROUND(29); TF_ROUND(16); TF_ROUND(24);
    x0 += k2; x1 += k0 + 2u;
    TF_ROUND(13); TF_ROUND(15); TF_ROUND(26); TF_ROUND(6);
    x0 += k0; x1 += k1 + 3u;
    TF_ROUND(17); TF_ROUND(29); TF_ROUND(16); TF_ROUND(24);
    x0 += k1; x1 += k2 + 4u;
    TF_ROUND(13); TF_ROUND(15); TF_ROUND(26); TF_ROUND(6);
    x0 += k2; x1 += k0 + 5u;
    return x0 ^ x1;
}

// bits -> float in [0, 1-2^-23]
__device__ __forceinline__ float bits_to_unit(unsigned b) {
    return __uint_as_float((b >> 9) | 0x3f800000u) - 1.0f;
}

// XLA ErfInv32 (Giles polynomial), fast-log variant
__device__ __forceinline__ float erfinv_xla(float x) {
    float w = -__logf(fmaf(-x, x, 1.0f));
    float p;
    if (w < 5.0f) {
        w = w - 2.5f;
        p = 2.81022636e-08f;
        p = fmaf(p, w, 3.43273939e-07f);
        p = fmaf(p, w, -3.5233877e-06f);
        p = fmaf(p, w, -4.39150654e-06f);
        p = fmaf(p, w, 0.00021858087f);
        p = fmaf(p, w, -0.00125372503f);
        p = fmaf(p, w, -0.00417768164f);
        p = fmaf(p, w, 0.246640727f);
        p = fmaf(p, w, 1.50140941f);
    } else {
        w = sqrtf(w) - 3.0f;
        p = -0.000200214257f;
        p = fmaf(p, w, 0.000100950558f);
        p = fmaf(p, w, 0.00134934322f);
        p = fmaf(p, w, -0.00367342844f);
        p = fmaf(p, w, 0.00573950773f);
        p = fmaf(p, w, -0.0076224613f);
        p = fmaf(p, w, 0.00943887047f);
        p = fmaf(p, w, 1.00167406f);
        p = fmaf(p, w, 2.83297682f);
    }
    return p * x;
}

__device__ __forceinline__ float normal_from_bits(unsigned b) {
    float f = bits_to_unit(b);
    float u = fmaf(f, 2.0f, -0.99999994f);
    u = fmaxf(-0.99999994f, u);
    return 1.41421356f * erfinv_xla(u);
}

__device__ __forceinline__ float gumbel_from_bits(unsigned b) {
    float f = bits_to_unit(b);
    float t = -__logf(fmaxf(f, 1.17549435e-38f));
    t = fmaxf(t, 1.17549435e-38f);
    return -__logf(t);
}

// Coalesced flush: 32 rows x 16 tile cols -> gmem, 16 sectors per STG.128.
__device__ __forceinline__ void flush_tile(const float* tile, float* gbase,
                                           int stride, int c0, int lane) {
#pragma unroll
    for (int it = 0; it < 4; it++) {
        const int row = it * 8 + (lane >> 2);
        const int col = (lane & 3) * 4;
        float4 v = *(const float4*)(tile + row * 20 + col);
        *(float4*)(gbase + (size_t)row * stride + c0 + col) = v;
    }
}

// ==================== mask bit-pack pre-kernel ====================
// Warp handles 2 rows: lane l reads int4 at flat index (coalesced),
// forms a 4-bit nibble, OR-reduces nibbles across each 16-lane half.
__global__ __launch_bounds__(256)
void pack_mask_kernel(const int4* __restrict__ mask4) {
    const int gw = (blockIdx.x * 256 + threadIdx.x) >> 5;   // global warp id
    const int lane = threadIdx.x & 31;
    const int f = gw * 32 + lane;                           // int4 flat index
    int4 m = mask4[f];
    unsigned nib = (unsigned)(m.x & 1) | ((unsigned)(m.y & 1) << 1)
                 | ((unsigned)(m.z & 1) << 2) | ((unsigned)(m.w & 1) << 3);
    u64t part = (u64t)nib << ((lane & 15) * 4);
#pragma unroll
    for (int off = 1; off < 16; off <<= 1)
        part |= __shfl_xor_sync(0xffffffffu, part, off);
    if ((lane & 15) == 0)
        g_packed_mask[gw * 2 + (lane >> 4)] = part;
}

__global__ __launch_bounds__(256, 2)
void decoder_kernel(const float* __restrict__ y_lat, const float* __restrict__ samp_s,
                    const float* __restrict__ onehot,
                    const float* __restrict__ W_pz, const float* __restrict__ b_pz,
                    const float* __restrict__ W_real, const float* __restrict__ b_real,
                    const float* __restrict__ W_cat, const float* __restrict__ b_cat,
                    float* __restrict__ out,
                    unsigned kn0, unsigned kn1, unsigned kn2,
                    unsigned kg0, unsigned kg1, unsigned kg2) {
    extern __shared__ float sm[];
    {
        const int tid = threadIdx.x;
        const int nt = blockDim.x;
        for (int i = tid; i < 256; i += nt)
            ((float4*)(sm + SM_WPZ))[i] = ((const float4*)W_pz)[i];
        // transpose W_real [r][d][o] -> [r][o][d]
        for (int i = tid; i < 4096; i += nt) {
            int r = i >> 7, o = (i >> 6) & 1, d = i & 63;
            sm[SM_WR + i] = W_real[(r << 7) + (d << 1) + o];
        }
        // transpose W_cat [c][d][k] -> [c][k][d]
        for (int i = tid; i < 8192; i += nt) {
            int c = i >> 8, k = (i >> 6) & 3, d = i & 63;
            sm[SM_WC + i] = W_cat[(c << 8) + (d << 2) + k];
        }
        for (int i = tid; i < 8; i += nt)
            ((float4*)(sm + SM_BPZ))[i] = ((const float4*)b_pz)[i];
        for (int i = tid; i < 16; i += nt)
            ((float4*)(sm + SM_BR))[i] = ((const float4*)b_real)[i];
        for (int i = tid; i < 32; i += nt)
            ((float4*)(sm + SM_BC))[i] = ((const float4*)b_cat)[i];
    }
    __syncthreads();

    const int b = blockIdx.x * 256 + threadIdx.x;
    const int lane = threadIdx.x & 31;
    const int warp = threadIdx.x >> 5;
    const int rowbase = b & ~31;

    float* tileA = sm + SM_TILEA + warp * 640;
    float* tileB = sm + SM_TILEB + warp * 640;

    float* o_out = out;
    float* o_mpz = out + (size_t)B_TOTAL * 64;
    float* o_lvz = out + (size_t)B_TOTAL * 96;
    float* o_lpx = out + (size_t)B_TOTAL * 128;

    // ================= pz: mean_pz = s @ W_pz^T + b_pz =================
    {
        u64t s2[16];
        const ulonglong2* ps = (const ulonglong2*)(samp_s + (size_t)b * SN);
#pragma unroll
        for (int i = 0; i < 8; i++) {
            ulonglong2 v = ps[i]; s2[2*i] = v.x; s2[2*i+1] = v.y;
        }
#pragma unroll 1
        for (int z = 0; z < ZN; z++) {
            u64t acc = 0;
            const ulonglong2* w = (const ulonglong2*)(sm + SM_WPZ + z * SN);
#pragma unroll
            for (int j = 0; j < 8; j++) {   // 8 x 4 floats = 32 = SN
                ulonglong2 v = w[j];
                acc = ffma2(s2[2*j],   v.x, acc);
                acc = ffma2(s2[2*j+1], v.y, acc);
            }
            tileA[lane * 20 + (z & 15)] = sm[SM_BPZ + z] + pair_sum(acc);
            if ((z & 15) == 15) {
                __syncwarp();
                flush_tile(tileA, o_mpz + (size_t)rowbase * 32, 32, z & 16, lane);
                __syncwarp();
            }
        }
    }

    // ================= log_var_pz = 0 (coalesced direct stores) =================
    {
        const float4 z4 = make_float4(0.f, 0.f, 0.f, 0.f);
        float* base = o_lvz + (size_t)rowbase * 32;
#pragma unroll
        for (int it = 0; it < 8; it++) {
            const int row = it * 4 + (lane >> 3);
            const int col = (lane & 7) * 4;
            *(float4*)(base + (size_t)row * 32 + col) = z4;
        }
    }

    // ================= packed miss mask (coalesced LDG.64 per row) =============
    const u64t pm = g_packed_mask[b];

    // ================= load y as K-pairs (register resident) =================
    u64t y2[32];
    {
        const ulonglong2* py = (const ulonglong2*)(y_lat + (size_t)b * D_DIM);
#pragma unroll
        for (int i = 0; i < 16; i++) {
            ulonglong2 v = py[i]; y2[2*i] = v.x; y2[2*i+1] = v.y;
        }
    }

    // ================= real features =================
#pragma unroll 1
    for (int r4 = 0; r4 < NR; r4 += 4) {
        float4 d4 = *(const float4*)(onehot + (size_t)b * 192 + r4);
        float darr[4] = {d4.x, d4.y, d4.z, d4.w};
        float outv[4], lpv[4];
#pragma unroll
        for (int rr = 0; rr < 4; rr++) {
            const int r = r4 + rr;
            u64t am = 0, av = 0;
            const ulonglong2* wm = (const ulonglong2*)(sm + SM_WR + r * 128);
            const ulonglong2* wv = wm + 16;   // +64 floats (16 x 16B)
#pragma unroll
            for (int j = 0; j < 16; j++) {    // 16 x 4 floats = 64 = D_DIM
                ulonglong2 m2 = wm[j], v2 = wv[j];
                am = ffma2(y2[2*j],   m2.x, am);
                am = ffma2(y2[2*j+1], m2.y, am);
                av = ffma2(y2[2*j],   v2.x, av);
                av = ffma2(y2[2*j+1], v2.y, av);
            }
            const float mu = sm[SM_BR + 2*r]     + pair_sum(am);
            const float lv = sm[SM_BR + 2*r + 1] + pair_sum(av);

            const float nz = normal_from_bits(tf_fold(kn0, kn1, kn2,
                                              (unsigned)b * 32u + (unsigned)r));
            float dv = darr[rr]; if (dv != dv) dv = 0.f;   // nan_to_num
            const float miss = (float)((unsigned)((pm >> r) & 1ull));
            const float diff = dv - mu;
            lpv[rr]  = -0.5f * ((1.8378770664f + lv) + diff * diff * __expf(-lv)) * miss;
            outv[rr] = fmaf(__expf(0.5f * lv), nz, mu);
        }
        *(float4*)(tileA + lane * 20 + (r4 & 12)) = make_float4(outv[0], outv[1], outv[2], outv[3]);
        *(float4*)(tileB + lane * 20 + (r4 & 12)) = make_float4(lpv[0], lpv[1], lpv[2], lpv[3]);
        if ((r4 & 12) == 12) {
            __syncwarp();
            flush_tile(tileA, o_out + (size_t)rowbase * 64, 64, r4 & 16, lane);
            flush_tile(tileB, o_lpx + (size_t)rowbase * 64, 64, r4 & 16, lane);
            __syncwarp();
        }
    }

    // ================= categorical features (groups of 4) =================
#pragma unroll 1
    for (int g = 0; g < 8; g++) {
        const float4* pd4 = (const float4*)(onehot + (size_t)b * 192 + 32 + 20 * g);
        float dat[20];
        *(float4*)(dat +  0) = pd4[0];
        *(float4*)(dat +  4) = pd4[1];
        *(float4*)(dat +  8) = pd4[2];
        *(float4*)(dat + 12) = pd4[3];
        *(float4*)(dat + 16) = pd4[4];
#pragma unroll
        for (int cc = 0; cc < 4; cc++) {
            const int c = 4 * g + cc;
            u64t a1 = 0, a2 = 0, a3 = 0, a4 = 0;
            const ulonglong2* w1 = (const ulonglong2*)(sm + SM_WC + c * 256);
            const ulonglong2* w2 = w1 + 16;   // +64 floats
            const ulonglong2* w3 = w1 + 32;   // +128 floats
            const ulonglong2* w4 = w1 + 48;   // +192 floats
#pragma unroll
            for (int j = 0; j < 16; j++) {    // 16 x 4 floats = 64 = D_DIM
                ulonglong2 p1 = w1[j], p2 = w2[j], p3 = w3[j], p4 = w4[j];
                a1 = ffma2(y2[2*j],   p1.x, a1);
                a1 = ffma2(y2[2*j+1], p1.y, a1);
                a2 = ffma2(y2[2*j],   p2.x, a2);
                a2 = ffma2(y2[2*j+1], p2.y, a2);
                a3 = ffma2(y2[2*j],   p3.x, a3);
                a3 = ffma2(y2[2*j+1], p3.y, a3);
                a4 = ffma2(y2[2*j],   p4.x, a4);
                a4 = ffma2(y2[2*j+1], p4.y, a4);
            }
            float4 bc = *(const float4*)(sm + SM_BC + 4 * c);
            const float l1 = bc.x + pair_sum(a1);
            const float l2 = bc.y + pair_sum(a2);
            const float l3 = bc.z + pair_sum(a3);
            const float l4 = bc.w + pair_sum(a4);

            // ---- softmax log-prob ----
            const float* data5 = dat + 5 * cc;
            const float miss = (float)((unsigned)((pm >> (32 + c)) & 1ull));
            float m = fmaxf(0.0f, fmaxf(fmaxf(l1, l2), fmaxf(l3, l4)));
            float e0 = __expf(0.0f - m);
            float e1 = __expf(l1 - m);
            float e2 = __expf(l2 - m);
            float e3 = __expf(l3 - m);
            float e4 = __expf(l4 - m);
            float logS = __logf(((e0 + e1) + (e2 + e3)) + e4);
            float lp =            data5[0] * ((0.0f - m) - logS);
            lp = fmaf(data5[1], (l1 - m) - logS, lp);
            lp = fmaf(data5[2], (l2 - m) - logS, lp);
            lp = fmaf(data5[3], (l3 - m) - logS, lp);
            lp = fmaf(data5[4], (l4 - m) - logS, lp);

            // ---- gumbel argmax, folds consumed inline ----
            const unsigned base = ((unsigned)b * 32u + (unsigned)c) * 5u;
            float best = gumbel_from_bits(tf_fold(kg0, kg1, kg2, base));
            int arg = 0;
            float z1 = l1 + gumbel_from_bits(tf_fold(kg0, kg1, kg2, base + 1u));
            if (z1 > best) { best = z1; arg = 1; }
            float z2 = l2 + gumbel_from_bits(tf_fold(kg0, kg1, kg2, base + 2u));
            if (z2 > best) { best = z2; arg = 2; }
            float z3 = l3 + gumbel_from_bits(tf_fold(kg0, kg1, kg2, base + 3u));
            if (z3 > best) { best = z3; arg = 3; }
            float z4 = l4 + gumbel_from_bits(tf_fold(kg0, kg1, kg2, base + 4u));
            if (z4 > best) { best = z4; arg = 4; }

            tileA[lane * 20 + (c & 15)] = (float)arg;
            tileB[lane * 20 + (c & 15)] = lp * miss;
        }
        if ((g & 3) == 3) {
            __syncwarp();
            const int c0 = 32 + ((g & 4) ? 16 : 0);
            flush_tile(tileA, o_out + (size_t)rowbase * 64, 64, c0, lane);
            flush_tile(tileB, o_lpx + (size_t)rowbase * 64, 64, c0, lane);
            __syncwarp();
        }
    }
}

extern "C" void kernel_launch(void* const* d_in, const int* in_sizes, int n_in,
                              void* d_out, int out_size) {
    const float* y_lat  = (const float*)d_in[0];
    const float* samp_s = (const float*)d_in[1];
    const float* onehot = (const float*)d_in[2];
    // d_in[3] = static_types (compile-time known layout; unused)
    const int*   mask   = (const int*)d_in[4];
    const float* W_pz   = (const float*)d_in[5];
    const float* b_pz   = (const float*)d_in[6];
    const float* W_real = (const float*)d_in[7];
    const float* b_real = (const float*)d_in[8];
    const float* W_cat  = (const float*)d_in[9];
    const float* b_cat  = (const float*)d_in[10];
    float* out = (float*)d_out;

    // jax.random.key(42) = (0, 42); partitionable (foldlike) split:
    // key_i = threefry((0,42), (0, i)), both output words form the subkey.
    unsigned kn0, kn1, kg0, kg1;
    threefry_full(0u, 42u, 0u, 0u, kn0, kn1);   // k_norm
    threefry_full(0u, 42u, 0u, 1u, kg0, kg1);   // k_gum
    const unsigned kn2 = kn0 ^ kn1 ^ 0x1BD11BDAu;
    const unsigned kg2 = kg0 ^ kg1 ^ 0x1BD11BDAu;

    // 1) pack miss mask: B rows -> B u64 words (coalesced reads)
    // warps = B/2 -> threads = B*16 -> blocks = B*16/256
    pack_mask_kernel<<<(B_TOTAL * 16) / 256, 256>>>((const int4*)mask);

    // 2) main kernel
    cudaFuncSetAttribute(decoder_kernel,
                         cudaFuncAttributeMaxDynamicSharedMemorySize, SM_TOTAL * 4);
    decoder_kernel<<<B_TOTAL / 256, 256, SM_TOTAL * 4>>>(
        y_lat, samp_s, onehot, W_pz, b_pz, W_real, b_real, W_cat, b_cat,
        out, kn0, kn1, kn2, kg0, kg1, kg2);
}

// round 17
// speedup vs baseline: 1.1987x; 1.0414x over previous
#include <cuda_runtime.h>
#include <cstdint>

#define B_TOTAL 262144
#define D_DIM   64
#define NR      32
#define NC      32
#define SN      32
#define ZN      32

typedef unsigned long long u64t;

// shared memory layout in floats
#define SM_WPZ   0          // 1024  W_pz[z][j]
#define SM_WR    1024       // 4096  W_real[r][o][d] (transposed)
#define SM_WC    5120       // 8192  W_cat[c][k][d]  (transposed)
#define SM_BPZ   13312      // 32
#define SM_BR    13344      // 64
#define SM_BC    13408      // 128
#define SM_TILEA 13536      // 8 warps x 640 floats (32 rows x 20 stride)
#define SM_TILEB 18656      // 8 warps x 640 floats
#define SM_TOTAL 23776      // floats -> 95104 bytes

// ---------------- packed f32x2 helpers ----------------
__device__ __forceinline__ u64t ffma2(u64t a, u64t b, u64t c) {
    u64t d;
    asm("fma.rn.f32x2 %0, %1, %2, %3;" : "=l"(d) : "l"(a), "l"(b), "l"(c));
    return d;
}
__device__ __forceinline__ float pair_sum(u64t v) {
    unsigned lo, hi;
    asm("mov.b64 {%0, %1}, %2;" : "=r"(lo), "=r"(hi) : "l"(v));
    return __uint_as_float(lo) + __uint_as_float(hi);
}

// ---------------- threefry2x32 (JAX schedule) ----------------
#define TF_ROUND(r) do { x0 += x1; x1 = (x1 << (r)) | (x1 >> (32 - (r))); x1 ^= x0; } while (0)

__host__ __device__ __forceinline__ void threefry_full(unsigned k0, unsigned k1,
                                                       unsigned x0, unsigned x1,
                                                       unsigned &o0, unsigned &o1) {
    const unsigned k2 = k0 ^ k1 ^ 0x1BD11BDAu;
    x0 += k0; x1 += k1;
    TF_ROUND(13); TF_ROUND(15); TF_ROUND(26); TF_ROUND(6);
    x0 += k1; x1 += k2 + 1u;
    TF_ROUND(17); TF_ROUND(29); TF_ROUND(16); TF_ROUND(24);
    x0 += k2; x1 += k0 + 2u;
    TF_ROUND(13); TF_ROUND(15); TF_ROUND(26); TF_ROUND(6);
    x0 += k0; x1 += k1 + 3u;
    TF_ROUND(17); TF_ROUND(29); TF_ROUND(16); TF_ROUND(24);
    x0 += k1; x1 += k2 + 4u;
    TF_ROUND(13); TF_ROUND(15); TF_ROUND(26); TF_ROUND(6);
    x0 += k2; x1 += k0 + 5u;
    o0 = x0; o1 = x1;
}

// Partitionable threefry sample: counter (hi=0, lo=ctr), folded o0^o1.
__device__ __forceinline__ unsigned tf_fold(unsigned k0, unsigned k1, unsigned k2,
                                            unsigned ctr) {
    unsigned x0 = k0;
    unsigned x1 = ctr + k1;
    TF_ROUND(13); TF_ROUND(15); TF_ROUND(26); TF_ROUND(6);
    x0 += k1; x1 += k2 + 1u;
    TF_ROUND(17); TF_ROUND(29); TF_ROUND(16); TF_ROUND(24);
    x0 += k2; x1 += k0 + 2u;
    TF_ROUND(13); TF_ROUND(15); TF_ROUND(26); TF_ROUND(6);
    x0 += k0; x1 += k1 + 3u;
    TF_ROUND(17); TF_ROUND(29); TF_ROUND(16); TF_ROUND(24);
    x0 += k1; x1 += k2 + 4u;
    TF_ROUND(13); TF_ROUND(15); TF_ROUND(26); TF_ROUND(6);
    x0 += k2; x1 += k0 + 5u;
    return x0 ^ x1;
}

// bits -> float in [0, 1-2^-23]
__device__ __forceinline__ float bits_to_unit(unsigned b) {
    return __uint_as_float((b >> 9) | 0x3f800000u) - 1.0f;
}

// XLA ErfInv32 (Giles polynomial), fast-log variant
__device__ __forceinline__ float erfinv_xla(float x) {
    float w = -__logf(fmaf(-x, x, 1.0f));
    float p;
    if (w < 5.0f) {
        w = w - 2.5f;
        p = 2.81022636e-08f;
        p = fmaf(p, w, 3.43273939e-07f);
        p = fmaf(p, w, -3.5233877e-06f);
        p = fmaf(p, w, -4.39150654e-06f);
        p = fmaf(p, w, 0.00021858087f);
        p = fmaf(p, w, -0.00125372503f);
        p = fmaf(p, w, -0.00417768164f);
        p = fmaf(p, w, 0.246640727f);
        p = fmaf(p, w, 1.50140941f);
    } else {
        w = sqrtf(w) - 3.0f;
        p = -0.000200214257f;
        p = fmaf(p, w, 0.000100950558f);
        p = fmaf(p, w, 0.00134934322f);
        p = fmaf(p, w, -0.00367342844f);
        p = fmaf(p, w, 0.00573950773f);
        p = fmaf(p, w, -0.0076224613f);
        p = fmaf(p, w, 0.00943887047f);
        p = fmaf(p, w, 1.00167406f);
        p = fmaf(p, w, 2.83297682f);
    }
    return p * x;
}

__device__ __forceinline__ float normal_from_bits(unsigned b) {
    float f = bits_to_unit(b);
    float u = fmaf(f, 2.0f, -0.99999994f);
    u = fmaxf(-0.99999994f, u);
    return 1.41421356f * erfinv_xla(u);
}

__device__ __forceinline__ float gumbel_from_bits(unsigned b) {
    float f = bits_to_unit(b);
    float t = -__logf(fmaxf(f, 1.17549435e-38f));
    t = fmaxf(t, 1.17549435e-38f);
    return -__logf(t);
}

// Coalesced flush: 32 rows x 16 tile cols -> gmem, 16 sectors per STG.128.
__device__ __forceinline__ void flush_tile(const float* tile, float* gbase,
                                           int stride, int c0, int lane) {
#pragma unroll
    for (int it = 0; it < 4; it++) {
        const int row = it * 8 + (lane >> 2);
        const int col = (lane & 3) * 4;
        float4 v = *(const float4*)(tile + row * 20 + col);
        *(float4*)(gbase + (size_t)row * stride + c0 + col) = v;
    }
}

__global__ __launch_bounds__(256, 2)
void decoder_kernel(const float* __restrict__ y_lat, const float* __restrict__ samp_s,
                    const float* __restrict__ onehot, const int* __restrict__ miss_mask,
                    const float* __restrict__ W_pz, const float* __restrict__ b_pz,
                    const float* __restrict__ W_real, const float* __restrict__ b_real,
                    const float* __restrict__ W_cat, const float* __restrict__ b_cat,
                    float* __restrict__ out,
                    unsigned kn0, unsigned kn1, unsigned kn2,
                    unsigned kg0, unsigned kg1, unsigned kg2) {
    extern __shared__ float sm[];
    {
        const int tid = threadIdx.x;
        const int nt = blockDim.x;
        for (int i = tid; i < 256; i += nt)
            ((float4*)(sm + SM_WPZ))[i] = ((const float4*)W_pz)[i];
        // transpose W_real [r][d][o] -> [r][o][d]
        for (int i = tid; i < 4096; i += nt) {
            int r = i >> 7, o = (i >> 6) & 1, d = i & 63;
            sm[SM_WR + i] = W_real[(r << 7) + (d << 1) + o];
        }
        // transpose W_cat [c][d][k] -> [c][k][d]
        for (int i = tid; i < 8192; i += nt) {
            int c = i >> 8, k = (i >> 6) & 3, d = i & 63;
            sm[SM_WC + i] = W_cat[(c << 8) + (d << 2) + k];
        }
        for (int i = tid; i < 8; i += nt)
            ((float4*)(sm + SM_BPZ))[i] = ((const float4*)b_pz)[i];
        for (int i = tid; i < 16; i += nt)
            ((float4*)(sm + SM_BR))[i] = ((const float4*)b_real)[i];
        for (int i = tid; i < 32; i += nt)
            ((float4*)(sm + SM_BC))[i] = ((const float4*)b_cat)[i];
    }
    __syncthreads();

    const int b = blockIdx.x * 256 + threadIdx.x;
    const int lane = threadIdx.x & 31;
    const int warp = threadIdx.x >> 5;
    const int rowbase = b & ~31;

    float* tileA = sm + SM_TILEA + warp * 640;
    float* tileB = sm + SM_TILEB + warp * 640;

    float* o_out = out;
    float* o_mpz = out + (size_t)B_TOTAL * 64;
    float* o_lvz = out + (size_t)B_TOTAL * 96;
    float* o_lpx = out + (size_t)B_TOTAL * 128;

    // ================= pz: mean_pz = s @ W_pz^T + b_pz =================
    {
        u64t s2[16];
        const ulonglong2* ps = (const ulonglong2*)(samp_s + (size_t)b * SN);
#pragma unroll
        for (int i = 0; i < 8; i++) {
            ulonglong2 v = ps[i]; s2[2*i] = v.x; s2[2*i+1] = v.y;
        }
#pragma unroll 1
        for (int z = 0; z < ZN; z++) {
            u64t acc = 0;
            const ulonglong2* w = (const ulonglong2*)(sm + SM_WPZ + z * SN);
#pragma unroll
            for (int j = 0; j < 8; j++) {   // 8 x 4 floats = 32 = SN
                ulonglong2 v = w[j];
                acc = ffma2(s2[2*j],   v.x, acc);
                acc = ffma2(s2[2*j+1], v.y, acc);
            }
            tileA[lane * 20 + (z & 15)] = sm[SM_BPZ + z] + pair_sum(acc);
            if ((z & 15) == 15) {
                __syncwarp();
                flush_tile(tileA, o_mpz + (size_t)rowbase * 32, 32, z & 16, lane);
                __syncwarp();
            }
        }
    }

    // ================= log_var_pz = 0 (coalesced direct stores) =================
    {
        const float4 z4 = make_float4(0.f, 0.f, 0.f, 0.f);
        float* base = o_lvz + (size_t)rowbase * 32;
#pragma unroll
        for (int it = 0; it < 8; it++) {
            const int row = it * 4 + (lane >> 3);
            const int col = (lane & 7) * 4;
            *(float4*)(base + (size_t)row * 32 + col) = z4;
        }
    }

    // ======== warp-cooperative miss-mask pack: 32 rows -> 32 u64 (coalesced) ====
    // Iteration it reads int4 flat indices rowbase*16 + it*32 + lane (coalesced),
    // covering rows rowbase+2*it and rowbase+2*it+1; lane&15 = chunk within row.
    // Nibble-ballot OR-reduce over each 16-lane half, result staged in tileA.
    u64t pm;
    {
        const int4* m4 = (const int4*)miss_mask + (size_t)rowbase * 16;
        u64t* packbuf = (u64t*)tileA;
#pragma unroll
        for (int it = 0; it < 16; it++) {
            int4 m = m4[it * 32 + lane];
            unsigned nib = (unsigned)(m.x & 1) | ((unsigned)(m.y & 1) << 1)
                         | ((unsigned)(m.z & 1) << 2) | ((unsigned)(m.w & 1) << 3);
            u64t part = (u64t)nib << ((lane & 15) * 4);
#pragma unroll
            for (int off = 1; off < 16; off <<= 1)
                part |= __shfl_xor_sync(0xffffffffu, part, off);
            if ((lane & 15) == 0)
                packbuf[it * 2 + (lane >> 4)] = part;
        }
        __syncwarp();
        pm = packbuf[lane];
        __syncwarp();
    }

    // ================= load y as K-pairs (register resident) =================
    u64t y2[32];
    {
        const ulonglong2* py = (const ulonglong2*)(y_lat + (size_t)b * D_DIM);
#pragma unroll
        for (int i = 0; i < 16; i++) {
            ulonglong2 v = py[i]; y2[2*i] = v.x; y2[2*i+1] = v.y;
        }
    }

    // ================= real features =================
#pragma unroll 1
    for (int r4 = 0; r4 < NR; r4 += 4) {
        float4 d4 = *(const float4*)(onehot + (size_t)b * 192 + r4);
        float darr[4] = {d4.x, d4.y, d4.z, d4.w};
        float outv[4], lpv[4];
#pragma unroll
        for (int rr = 0; rr < 4; rr++) {
            const int r = r4 + rr;
            u64t am = 0, av = 0;
            const ulonglong2* wm = (const ulonglong2*)(sm + SM_WR + r * 128);
            const ulonglong2* wv = wm + 16;   // +64 floats (16 x 16B)
#pragma unroll
            for (int j = 0; j < 16; j++) {    // 16 x 4 floats = 64 = D_DIM
                ulonglong2 m2 = wm[j], v2 = wv[j];
                am = ffma2(y2[2*j],   m2.x, am);
                am = ffma2(y2[2*j+1], m2.y, am);
                av = ffma2(y2[2*j],   v2.x, av);
                av = ffma2(y2[2*j+1], v2.y, av);
            }
            const float mu = sm[SM_BR + 2*r]     + pair_sum(am);
            const float lv = sm[SM_BR + 2*r + 1] + pair_sum(av);

            const float nz = normal_from_bits(tf_fold(kn0, kn1, kn2,
                                              (unsigned)b * 32u + (unsigned)r));
            float dv = darr[rr]; if (dv != dv) dv = 0.f;   // nan_to_num
            const float miss = (float)((unsigned)((pm >> r) & 1ull));
            const float diff = dv - mu;
            lpv[rr]  = -0.5f * ((1.8378770664f + lv) + diff * diff * __expf(-lv)) * miss;
            outv[rr] = fmaf(__expf(0.5f * lv), nz, mu);
        }
        *(float4*)(tileA + lane * 20 + (r4 & 12)) = make_float4(outv[0], outv[1], outv[2], outv[3]);
        *(float4*)(tileB + lane * 20 + (r4 & 12)) = make_float4(lpv[0], lpv[1], lpv[2], lpv[3]);
        if ((r4 & 12) == 12) {
            __syncwarp();
            flush_tile(tileA, o_out + (size_t)rowbase * 64, 64, r4 & 16, lane);
            flush_tile(tileB, o_lpx + (size_t)rowbase * 64, 64, r4 & 16, lane);
            __syncwarp();
        }
    }

    // ================= categorical features (groups of 4) =================
#pragma unroll 1
    for (int g = 0; g < 8; g++) {
        const float4* pd4 = (const float4*)(onehot + (size_t)b * 192 + 32 + 20 * g);
        float dat[20];
        *(float4*)(dat +  0) = pd4[0];
        *(float4*)(dat +  4) = pd4[1];
        *(float4*)(dat +  8) = pd4[2];
        *(float4*)(dat + 12) = pd4[3];
        *(float4*)(dat + 16) = pd4[4];
#pragma unroll
        for (int cc = 0; cc < 4; cc++) {
            const int c = 4 * g + cc;
            u64t a1 = 0, a2 = 0, a3 = 0, a4 = 0;
            const ulonglong2* w1 = (const ulonglong2*)(sm + SM_WC + c * 256);
            const ulonglong2* w2 = w1 + 16;   // +64 floats
            const ulonglong2* w3 = w1 + 32;   // +128 floats
            const ulonglong2* w4 = w1 + 48;   // +192 floats
#pragma unroll
            for (int j = 0; j < 16; j++) {    // 16 x 4 floats = 64 = D_DIM
                ulonglong2 p1 = w1[j], p2 = w2[j], p3 = w3[j], p4 = w4[j];
                a1 = ffma2(y2[2*j],   p1.x, a1);
                a1 = ffma2(y2[2*j+1], p1.y, a1);
                a2 = ffma2(y2[2*j],   p2.x, a2);
                a2 = ffma2(y2[2*j+1], p2.y, a2);
                a3 = ffma2(y2[2*j],   p3.x, a3);
                a3 = ffma2(y2[2*j+1], p3.y, a3);
                a4 = ffma2(y2[2*j],   p4.x, a4);
                a4 = ffma2(y2[2*j+1], p4.y, a4);
            }
            float4 bc = *(const float4*)(sm + SM_BC + 4 * c);
            const float l1 = bc.x + pair_sum(a1);
            const float l2 = bc.y + pair_sum(a2);
            const float l3 = bc.z + pair_sum(a3);
            const float l4 = bc.w + pair_sum(a4);

            // ---- softmax log-prob ----
            const float* data5 = dat + 5 * cc;
            const float miss = (float)((unsigned)((pm >> (32 + c)) & 1ull));
            float m = fmaxf(0.0f, fmaxf(fmaxf(l1, l2), fmaxf(l3, l4)));
            float e0 = __expf(0.0f - m);
            float e1 = __expf(l1 - m);
            float e2 = __expf(l2 - m);
            float e3 = __expf(l3 - m);
            float e4 = __expf(l4 - m);
            float logS = __logf(((e0 + e1) + (e2 + e3)) + e4);
            float lp =            data5[0] * ((0.0f - m) - logS);
            lp = fmaf(data5[1], (l1 - m) - logS, lp);
            lp = fmaf(data5[2], (l2 - m) - logS, lp);
            lp = fmaf(data5[3], (l3 - m) - logS, lp);
            lp = fmaf(data5[4], (l4 - m) - logS, lp);

            // ---- gumbel argmax, folds consumed inline ----
            const unsigned base = ((unsigned)b * 32u + (unsigned)c) * 5u;
            float best = gumbel_from_bits(tf_fold(kg0, kg1, kg2, base));
            int arg = 0;
            float z1 = l1 + gumbel_from_bits(tf_fold(kg0, kg1, kg2, base + 1u));
            if (z1 > best) { best = z1; arg = 1; }
            float z2 = l2 + gumbel_from_bits(tf_fold(kg0, kg1, kg2, base + 2u));
            if (z2 > best) { best = z2; arg = 2; }
            float z3 = l3 + gumbel_from_bits(tf_fold(kg0, kg1, kg2, base + 3u));
            if (z3 > best) { best = z3; arg = 3; }
            float z4 = l4 + gumbel_from_bits(tf_fold(kg0, kg1, kg2, base + 4u));
            if (z4 > best) { best = z4; arg = 4; }

            tileA[lane * 20 + (c & 15)] = (float)arg;
            tileB[lane * 20 + (c & 15)] = lp * miss;
        }
        if ((g & 3) == 3) {
            __syncwarp();
            const int c0 = 32 + ((g & 4) ? 16 : 0);
            flush_tile(tileA, o_out + (size_t)rowbase * 64, 64, c0, lane);
            flush_tile(tileB, o_lpx + (size_t)rowbase * 64, 64, c0, lane);
            __syncwarp();
        }
    }
}

extern "C" void kernel_launch(void* const* d_in, const int* in_sizes, int n_in,
                              void* d_out, int out_size) {
    const float* y_lat  = (const float*)d_in[0];
    const float* samp_s = (const float*)d_in[1];
    const float* onehot = (const float*)d_in[2];
    // d_in[3] = static_types (compile-time known layout; unused)
    const int*   mask   = (const int*)d_in[4];
    const float* W_pz   = (const float*)d_in[5];
    const float* b_pz   = (const float*)d_in[6];
    const float* W_real = (const float*)d_in[7];
    const float* b_real = (const float*)d_in[8];
    const float* W_cat  = (const float*)d_in[9];
    const float* b_cat  = (const float*)d_in[10];
    float* out = (float*)d_out;

    // jax.random.key(42) = (0, 42); partitionable (foldlike) split:
    // key_i = threefry((0,42), (0, i)), both output words form the subkey.
    unsigned kn0, kn1, kg0, kg1;
    threefry_full(0u, 42u, 0u, 0u, kn0, kn1);   // k_norm
    threefry_full(0u, 42u, 0u, 1u, kg0, kg1);   // k_gum
    const unsigned kn2 = kn0 ^ kn1 ^ 0x1BD11BDAu;
    const unsigned kg2 = kg0 ^ kg1 ^ 0x1BD11BDAu;

    cudaFuncSetAttribute(decoder_kernel,
                         cudaFuncAttributeMaxDynamicSharedMemorySize, SM_TOTAL * 4);
    decoder_kernel<<<B_TOTAL / 256, 256, SM_TOTAL * 4>>>(
        y_lat, samp_s, onehot, mask, W_pz, b_pz, W_real, b_real, W_cat, b_cat,
        out, kn0, kn1, kn2, kg0, kg1, kg2);
}